// round 4
// baseline (speedup 1.0000x reference)
#include <cuda_runtime.h>
#include <math.h>

// Spherization, per row r (512 features):
//   ang_j = A*sigmoid(scaling*x) + phiL
//   out[k]   = radius * prod_{j<k}(sin(ang_j)+eps) * sgn(cos_k)*(|cos(ang_k)|+eps)
//   out[512] = radius * prod_j (sin(ang_j)+eps)
// Issue-count-optimized: Blackwell packed f32x2 for all non-MUFU math,
// 4 independent (ILP) warp scans, coalesced LDG/STS/LDS/STG.

#define NFEAT 512
#define ROW_OUT 513
#define SROW_PITCH 520
#define WPB 8
#define EPS_BITS 0x358637BDu   // bit pattern of 1e-6f

typedef unsigned long long u64;

static __device__ __forceinline__ u64 pk2(float a, float b) {
    u64 r; asm("mov.b64 %0, {%1,%2};" : "=l"(r) : "f"(a), "f"(b)); return r;
}
static __device__ __forceinline__ void up2(u64 v, float &a, float &b) {
    asm("mov.b64 {%0,%1}, %2;" : "=f"(a), "=f"(b) : "l"(v));
}
static __device__ __forceinline__ u64 mul2(u64 a, u64 b) {
    u64 r; asm("mul.rn.f32x2 %0, %1, %2;" : "=l"(r) : "l"(a), "l"(b)); return r;
}
static __device__ __forceinline__ u64 add2(u64 a, u64 b) {
    u64 r; asm("add.rn.f32x2 %0, %1, %2;" : "=l"(r) : "l"(a), "l"(b)); return r;
}
static __device__ __forceinline__ u64 fma2(u64 a, u64 b, u64 c) {
    u64 r; asm("fma.rn.f32x2 %0, %1, %2, %3;" : "=l"(r) : "l"(a), "l"(b), "l"(c)); return r;
}
static __device__ __forceinline__ u64 ex2x2(u64 a) {
    u64 r; asm("{\n\t.reg .f32 lo,hi;\n\tmov.b64 {lo,hi}, %1;\n\t"
               "ex2.approx.f32 lo, lo;\n\tex2.approx.f32 hi, hi;\n\t"
               "mov.b64 %0, {lo,hi};\n\t}" : "=l"(r) : "l"(a)); return r;
}
static __device__ __forceinline__ u64 rcpx2(u64 a) {
    u64 r; asm("{\n\t.reg .f32 lo,hi;\n\tmov.b64 {lo,hi}, %1;\n\t"
               "rcp.approx.f32 lo, lo;\n\trcp.approx.f32 hi, hi;\n\t"
               "mov.b64 %0, {lo,hi};\n\t}" : "=l"(r) : "l"(a)); return r;
}
static __device__ __forceinline__ u64 sinx2(u64 a) {
    u64 r; asm("{\n\t.reg .f32 lo,hi;\n\tmov.b64 {lo,hi}, %1;\n\t"
               "sin.approx.f32 lo, lo;\n\tsin.approx.f32 hi, hi;\n\t"
               "mov.b64 %0, {lo,hi};\n\t}" : "=l"(r) : "l"(a)); return r;
}
static __device__ __forceinline__ u64 cosx2(u64 a) {
    u64 r; asm("{\n\t.reg .f32 lo,hi;\n\tmov.b64 {lo,hi}, %1;\n\t"
               "cos.approx.f32 lo, lo;\n\tcos.approx.f32 hi, hi;\n\t"
               "mov.b64 %0, {lo,hi};\n\t}" : "=l"(r) : "l"(a)); return r;
}
// per half: (cs & 0x80000000) | eps_bits  -> one LOP3 each (LUT 0xEA = (a&b)|c)
static __device__ __forceinline__ u64 signeps2(u64 cs) {
    u64 r; asm("{\n\t.reg .b32 lo,hi,sl,sh;\n\tmov.b64 {lo,hi}, %1;\n\t"
               "lop3.b32 sl, lo, 0x80000000, 0x358637BD, 0xEA;\n\t"
               "lop3.b32 sh, hi, 0x80000000, 0x358637BD, 0xEA;\n\t"
               "mov.b64 %0, {sl,sh};\n\t}" : "=l"(r) : "l"(cs)); return r;
}

// sigmoid->angle->(sin+eps, cos+copysign(eps)) for two elements
static __device__ __forceinline__ void elem2(float a, float b,
                                             u64 cmul2, u64 A2, u64 phiL2,
                                             u64 one2, u64 eps2,
                                             u64 &sv2, u64 &cv2)
{
    u64 v2  = pk2(a, b);
    u64 t2  = mul2(v2, cmul2);      // t = -scaling*log2e * x
    u64 e2  = ex2x2(t2);            // e = exp(-scaling*x)
    u64 d2  = add2(e2, one2);
    u64 r2  = rcpx2(d2);            // sigmoid
    u64 an2 = fma2(A2, r2, phiL2);  // angle in [phiL, pi - phiL]
    u64 sn2 = sinx2(an2);           // > 0 on range
    u64 cs2 = cosx2(an2);
    sv2 = add2(sn2, eps2);
    cv2 = add2(cs2, signeps2(cs2)); // sgn(cs)*(|cs|+eps)
}

__global__ __launch_bounds__(WPB * 32)
void spherization_kernel(const float* __restrict__ x,
                         const float* __restrict__ scaling_p,
                         const float* __restrict__ radius_p,
                         float* __restrict__ out,
                         int nrows, float A, float phiL)
{
    __shared__ float sbuf[WPB * SROW_PITCH];

    const int wib  = threadIdx.x >> 5;
    const int lane = threadIdx.x & 31;
    const int row  = blockIdx.x * WPB + wib;
    if (row >= nrows) return;

    const float scaling = __ldg(scaling_p);
    const float radius  = __ldg(radius_p);
    const float cmul = -scaling * 1.4426950408889634f;

    const u64 cmul2 = pk2(cmul, cmul);
    const u64 A2    = pk2(A, A);
    const u64 phiL2 = pk2(phiL, phiL);
    const u64 one2  = pk2(1.0f, 1.0f);
    const float epsf = __uint_as_float(EPS_BITS);
    const u64 eps2  = pk2(epsf, epsf);

    const float4* xr = reinterpret_cast<const float4*>(x + (size_t)row * NFEAT);
    float* srow = sbuf + wib * SROW_PITCH;

    // prefetch all loads (MLP=4), coalesced LDG.128
    float4 v[4];
    #pragma unroll
    for (int j = 0; j < 4; j++) v[j] = xr[lane + 32 * j];

    u64 cvA[4], cvB[4];             // cos terms, packed pairs
    float s0a[4], p01a[4], s2a[4];  // prefix building blocks
    float tot[4];                   // per-lane block totals

    #pragma unroll
    for (int j = 0; j < 4; j++) {
        u64 svA, svB;
        elem2(v[j].x, v[j].y, cmul2, A2, phiL2, one2, eps2, svA, cvA[j]);
        elem2(v[j].z, v[j].w, cmul2, A2, phiL2, one2, eps2, svB, cvB[j]);
        float s0, s1, s2, s3;
        up2(svA, s0, s1); up2(svB, s2, s3);
        // {p01, p23} = {s0,s2} * {s1,s3}
        u64 pp = mul2(pk2(s0, s2), pk2(s1, s3));
        float q01, q23; up2(pp, q01, q23);
        s0a[j] = s0; p01a[j] = q01; s2a[j] = s2;
        tot[j] = q01 * q23;
    }

    // 4 independent warp-inclusive scans (ILP-4 on the shfl chains)
    float i0 = tot[0], i1 = tot[1], i2 = tot[2], i3 = tot[3];
    #pragma unroll
    for (int d = 1; d < 32; d <<= 1) {
        float t0 = __shfl_up_sync(0xFFFFFFFFu, i0, d);
        float t1 = __shfl_up_sync(0xFFFFFFFFu, i1, d);
        float t2 = __shfl_up_sync(0xFFFFFFFFu, i2, d);
        float t3 = __shfl_up_sync(0xFFFFFFFFu, i3, d);
        if (lane >= d) { i0 *= t0; i1 *= t1; i2 *= t2; i3 *= t3; }
    }
    float x0 = __shfl_up_sync(0xFFFFFFFFu, i0, 1);
    float x1 = __shfl_up_sync(0xFFFFFFFFu, i1, 1);
    float x2 = __shfl_up_sync(0xFFFFFFFFu, i2, 1);
    float x3 = __shfl_up_sync(0xFFFFFFFFu, i3, 1);
    if (lane == 0) { x0 = 1.0f; x1 = 1.0f; x2 = 1.0f; x3 = 1.0f; }
    float f0 = __shfl_sync(0xFFFFFFFFu, i0, 31);
    float f1 = __shfl_sync(0xFFFFFFFFu, i1, 31);
    float f2 = __shfl_sync(0xFFFFFFFFu, i2, 31);
    float f3 = __shfl_sync(0xFFFFFFFFu, i3, 31);

    // block carries
    float c0 = radius;
    float c1 = c0 * f0, c2 = c1 * f1, c3 = c2 * f2;
    u64 bp01 = mul2(pk2(c0, c1), pk2(x0, x1));
    u64 bp23 = mul2(pk2(c2, c3), pk2(x2, x3));
    float bp[4];
    up2(bp01, bp[0], bp[1]); up2(bp23, bp[2], bp[3]);

    #pragma unroll
    for (int j = 0; j < 4; j++) {
        float bpj = bp[j];
        // b1 = bp*s0, b2 = bp*p01 (packed), b3 = b2*s2
        u64 b12 = mul2(pk2(bpj, bpj), pk2(s0a[j], p01a[j]));
        float b1, b2; up2(b12, b1, b2);
        float b3 = b2 * s2a[j];
        u64 o01 = mul2(pk2(bpj, b1), cvA[j]);
        u64 o23 = mul2(pk2(b2, b3), cvB[j]);
        float o0, o1, o2, o3;
        up2(o01, o0, o1); up2(o23, o2, o3);
        reinterpret_cast<float4*>(srow)[lane + 32 * j] = make_float4(o0, o1, o2, o3);
    }
    if (lane == 0) srow[NFEAT] = c3 * f3;   // out[512] = radius * full product
    __syncwarp();

    // coalesced copy SMEM row -> GMEM
    float* orow = out + (size_t)row * ROW_OUT;
    #pragma unroll
    for (int it = 0; it < 16; it++)
        orow[lane + 32 * it] = srow[lane + 32 * it];
    if (lane == 0) orow[NFEAT] = srow[NFEAT];
}

extern "C" void kernel_launch(void* const* d_in, const int* in_sizes, int n_in,
                              void* d_out, int out_size)
{
    int xi = 0;
    for (int i = 0; i < n_in; i++) if (in_sizes[i] > in_sizes[xi]) xi = i;
    int others[2]; int no = 0;
    for (int i = 0; i < n_in && no < 2; i++) if (i != xi) others[no++] = i;

    const float* x   = (const float*)d_in[xi];
    const float* sc  = (const float*)d_in[others[0]];   // scaling
    const float* rad = (const float*)d_in[others[1]];   // radius

    float* out = (float*)d_out;
    int nrows = in_sizes[xi] / NFEAT;

    // constants in double; PI truncated exactly as in the reference
    const double PI_d = 3.141592;
    double phiL = asin(pow(1e-6, 1.0 / 512.0));
    double phiU = PI_d / 2.0 * (1.0 - 0.01);
    if (phiU < phiL) phiL = phiU;
    float A = (float)(PI_d - 2.0 * phiL);

    int blocks = (nrows + WPB - 1) / WPB;
    spherization_kernel<<<blocks, WPB * 32>>>(x, sc, rad, out, nrows, A, (float)phiL);
}

// round 5
// speedup vs baseline: 1.0442x; 1.0442x over previous
#include <cuda_runtime.h>
#include <math.h>

// Spherization, per row r (512 features):
//   ang_j = A*sigmoid(scaling*x) + phiL
//   out[k]   = radius * prod_{j<k}(sin(ang_j)+eps) * sgn(cos_k)*(|cos(ang_k)|+eps)
//   out[512] = radius * prod_j (sin(ang_j)+eps)
// Issue-minimized scalar pipeline: 1 FMUL + EX2 + FADD + RCP + FFMA + SIN + COS
// + FADD + LOP3 + FADD per element (4 MUFU kept: cheapest per issue slot).
// One warp per row, lane owns k = 128j+4l+m; 4 INDEPENDENT warp scans (ILP-4),
// coalesced LDG.128 / STS.128 / scalar LDS+STG readback, streaming stores.

#define NFEAT 512
#define ROW_OUT 513
#define SROW_PITCH 520
#define WPB 8
#define EPSf 1e-6f

__global__ __launch_bounds__(WPB * 32)
void spherization_kernel(const float* __restrict__ x,
                         const float* __restrict__ scaling_p,
                         const float* __restrict__ radius_p,
                         float* __restrict__ out,
                         int nrows, float A, float phiL)
{
    __shared__ float sbuf[WPB * SROW_PITCH];

    const int wib  = threadIdx.x >> 5;
    const int lane = threadIdx.x & 31;
    const int row  = blockIdx.x * WPB + wib;
    if (row >= nrows) return;

    const float scaling = __ldg(scaling_p);
    const float radius  = __ldg(radius_p);
    // e = exp(-scaling*x) = 2^(x * cmul) : single FMUL feeds EX2
    const float cmul = -scaling * 1.4426950408889634f;

    const float4* xr = reinterpret_cast<const float4*>(x + (size_t)row * NFEAT);
    float* srow = sbuf + wib * SROW_PITCH;

    // prefetch all loads (MLP=4), coalesced LDG.128
    float4 v[4];
    #pragma unroll
    for (int j = 0; j < 4; j++) v[j] = xr[lane + 32 * j];

    float s0a[4], e2a[4], e3a[4];   // local prefix pieces per block
    float cv0[4], cv1[4], cv2[4], cv3[4];
    float tot[4];

    #pragma unroll
    for (int j = 0; j < 4; j++) {
        float vv[4] = {v[j].x, v[j].y, v[j].z, v[j].w};
        float sv[4], cv[4];
        #pragma unroll
        for (int m = 0; m < 4; m++) {
            float t = vv[m] * cmul;
            float e;  asm("ex2.approx.f32 %0, %1;" : "=f"(e) : "f"(t));   // e=inf ok
            float d = e + 1.0f;
            float r;  asm("rcp.approx.f32 %0, %1;" : "=f"(r) : "f"(d));   // sigmoid
            float ang = fmaf(A, r, phiL);                 // in [phiL, pi - phiL]
            float sn  = __sinf(ang);                      // > 0 on range
            float cs  = __cosf(ang);
            sv[m] = sn + EPSf;
            // sgn(cs)*(|cs|+eps) = cs + ((cs & signbit) | eps_bits): LOP3 + FADD
            unsigned se;
            asm("lop3.b32 %0, %1, 0x80000000, 0x358637BD, 0xEA;"
                : "=r"(se) : "r"(__float_as_uint(cs)));
            cv[m] = cs + __uint_as_float(se);
        }
        float e1  = sv[0];
        float e2  = e1 * sv[1];
        float e3  = e2 * sv[2];
        s0a[j] = e1; e2a[j] = e2; e3a[j] = e3;
        tot[j] = e3 * sv[3];
        cv0[j] = cv[0]; cv1[j] = cv[1]; cv2[j] = cv[2]; cv3[j] = cv[3];
    }

    // 4 INDEPENDENT warp-inclusive scans (ILP-4 shfl chains)
    float i0 = tot[0], i1 = tot[1], i2 = tot[2], i3 = tot[3];
    #pragma unroll
    for (int d = 1; d < 32; d <<= 1) {
        float t0 = __shfl_up_sync(0xFFFFFFFFu, i0, d);
        float t1 = __shfl_up_sync(0xFFFFFFFFu, i1, d);
        float t2 = __shfl_up_sync(0xFFFFFFFFu, i2, d);
        float t3 = __shfl_up_sync(0xFFFFFFFFu, i3, d);
        if (lane >= d) { i0 *= t0; i1 *= t1; i2 *= t2; i3 *= t3; }
    }
    float x0 = __shfl_up_sync(0xFFFFFFFFu, i0, 1);
    float x1 = __shfl_up_sync(0xFFFFFFFFu, i1, 1);
    float x2 = __shfl_up_sync(0xFFFFFFFFu, i2, 1);
    float x3 = __shfl_up_sync(0xFFFFFFFFu, i3, 1);
    if (lane == 0) { x0 = 1.0f; x1 = 1.0f; x2 = 1.0f; x3 = 1.0f; }
    float f0 = __shfl_sync(0xFFFFFFFFu, i0, 31);
    float f1 = __shfl_sync(0xFFFFFFFFu, i1, 31);
    float f2 = __shfl_sync(0xFFFFFFFFu, i2, 31);
    float f3 = __shfl_sync(0xFFFFFFFFu, i3, 31);

    // block carries (scalar, short chain)
    float c0 = radius;
    float c1 = c0 * f0;
    float c2 = c1 * f1;
    float c3 = c2 * f2;
    float bp[4] = { c0 * x0, c1 * x1, c2 * x2, c3 * x3 };

    #pragma unroll
    for (int j = 0; j < 4; j++) {
        float bpj = bp[j];
        float4 o;
        o.x = bpj * cv0[j];
        o.y = (bpj * s0a[j]) * cv1[j];
        o.z = (bpj * e2a[j]) * cv2[j];
        o.w = (bpj * e3a[j]) * cv3[j];
        reinterpret_cast<float4*>(srow)[lane + 32 * j] = o;
    }
    if (lane == 0) srow[NFEAT] = c3 * f3;   // out[512] = radius * full product
    __syncwarp();

    // coalesced copy SMEM row -> GMEM, streaming (evict-first) stores
    float* orow = out + (size_t)row * ROW_OUT;
    #pragma unroll
    for (int it = 0; it < 16; it++)
        __stcs(orow + lane + 32 * it, srow[lane + 32 * it]);
    if (lane == 0) __stcs(orow + NFEAT, srow[NFEAT]);
}

extern "C" void kernel_launch(void* const* d_in, const int* in_sizes, int n_in,
                              void* d_out, int out_size)
{
    int xi = 0;
    for (int i = 0; i < n_in; i++) if (in_sizes[i] > in_sizes[xi]) xi = i;
    int others[2]; int no = 0;
    for (int i = 0; i < n_in && no < 2; i++) if (i != xi) others[no++] = i;

    const float* x   = (const float*)d_in[xi];
    const float* sc  = (const float*)d_in[others[0]];   // scaling
    const float* rad = (const float*)d_in[others[1]];   // radius

    float* out = (float*)d_out;
    int nrows = in_sizes[xi] / NFEAT;

    // constants in double; PI truncated exactly as in the reference
    const double PI_d = 3.141592;
    double phiL = asin(pow(1e-6, 1.0 / 512.0));
    double phiU = PI_d / 2.0 * (1.0 - 0.01);
    if (phiU < phiL) phiL = phiU;
    float A = (float)(PI_d - 2.0 * phiL);

    int blocks = (nrows + WPB - 1) / WPB;
    spherization_kernel<<<blocks, WPB * 32>>>(x, sc, rad, out, nrows, A, (float)phiL);
}

// round 6
// speedup vs baseline: 1.0847x; 1.0388x over previous
#include <cuda_runtime.h>
#include <math.h>

// Spherization, per row r (512 features):
//   ang_j = A*sigmoid(scaling*x) + phiL
//   out[k]   = radius * prod_{j<k}(sin(ang_j)+eps) * sgn(cos_k)*(|cos(ang_k)|+eps)
//   out[512] = radius * prod_j (sin(ang_j)+eps)
// R1 structure (best measured) with the sigmoid chain replaced by MUFU.TANH:
//   sigmoid(z) = (1+tanh(z/2))/2  =>  ang = fma(halfA, tanh(x*scaling/2), mid)
// Element pipeline: FMUL, TANH, FFMA, SIN, COS, FADD, |.|+eps/copysign.
// 3 MUFU + ~6 alu/fma issues per element. One warp per row; lane owns
// k = 128j+4l+m; 4 chained warp scans; SMEM-staged coalesced stores.

#define NFEAT 512
#define ROW_OUT 513
#define SROW_PITCH 520   // floats; 16B-aligned pitch
#define WARPS_PER_BLOCK 8
#define EPSf 1e-6f

__global__ __launch_bounds__(WARPS_PER_BLOCK * 32)
void spherization_kernel(const float* __restrict__ x,
                         const float* __restrict__ scaling_p,
                         const float* __restrict__ radius_p,
                         float* __restrict__ out,
                         int nrows, float halfA, float mid)
{
    __shared__ float sbuf[WARPS_PER_BLOCK * SROW_PITCH];

    const int wib  = threadIdx.x >> 5;
    const int lane = threadIdx.x & 31;
    const int row  = blockIdx.x * WARPS_PER_BLOCK + wib;
    if (row >= nrows) return;

    const float scaling = __ldg(scaling_p);
    const float radius  = __ldg(radius_p);
    const float hmul = 0.5f * scaling;     // t = hmul*x ; u = tanh(t)

    const float4* xr = reinterpret_cast<const float4*>(x + (size_t)row * NFEAT);
    float* srow = sbuf + wib * SROW_PITCH;

    // prefetch all loads (MLP=4)
    float4 v[4];
    #pragma unroll
    for (int j = 0; j < 4; j++) v[j] = xr[lane + 32 * j];

    float carry = radius;   // radius * (product of all elements in completed blocks)

    #pragma unroll
    for (int j = 0; j < 4; j++) {
        float vv[4] = {v[j].x, v[j].y, v[j].z, v[j].w};
        float sv[4], cv[4];
        #pragma unroll
        for (int m = 0; m < 4; m++) {
            float t = vv[m] * hmul;
            float u;  asm("tanh.approx.f32 %0, %1;" : "=f"(u) : "f"(t));
            float ang = fmaf(halfA, u, mid);          // in [phiL, pi - phiL]
            float sn  = __sinf(ang);                  // > 0 on range
            float cs  = __cosf(ang);
            sv[m] = sn + EPSf;
            cv[m] = copysignf(fabsf(cs) + EPSf, cs);
        }
        // local exclusive prefixes within the 4 owned elements
        float e1  = sv[0];
        float e2  = e1 * sv[1];
        float e3  = e2 * sv[2];
        float tot = e3 * sv[3];

        // warp-inclusive scan of per-lane block totals
        float incl = tot;
        #pragma unroll
        for (int d = 1; d < 32; d <<= 1) {
            float t2 = __shfl_up_sync(0xFFFFFFFFu, incl, d);
            if (lane >= d) incl *= t2;
        }
        float excl = __shfl_up_sync(0xFFFFFFFFu, incl, 1);
        if (lane == 0) excl = 1.0f;

        float bp = carry * excl;  // radius * prod of everything before this lane

        float4 o;
        o.x = bp * cv[0];
        o.y = (bp * e1) * cv[1];
        o.z = (bp * e2) * cv[2];
        o.w = (bp * e3) * cv[3];
        reinterpret_cast<float4*>(srow)[lane + 32 * j] = o;

        carry *= __shfl_sync(0xFFFFFFFFu, incl, 31);
    }
    if (lane == 0) srow[NFEAT] = carry;   // out[512] = radius * full product
    __syncwarp();

    // coalesced copy SMEM row -> GMEM (row pitch 513 floats)
    float* orow = out + (size_t)row * ROW_OUT;
    #pragma unroll
    for (int it = 0; it < 17; it++) {
        int c = lane + 32 * it;
        if (c < ROW_OUT) orow[c] = srow[c];
    }
}

extern "C" void kernel_launch(void* const* d_in, const int* in_sizes, int n_in,
                              void* d_out, int out_size)
{
    int xi = 0;
    for (int i = 0; i < n_in; i++) if (in_sizes[i] > in_sizes[xi]) xi = i;
    int others[2]; int no = 0;
    for (int i = 0; i < n_in && no < 2; i++) if (i != xi) others[no++] = i;

    const float* x   = (const float*)d_in[xi];
    const float* sc  = (const float*)d_in[others[0]];   // scaling
    const float* rad = (const float*)d_in[others[1]];   // radius

    float* out = (float*)d_out;
    int nrows = in_sizes[xi] / NFEAT;

    // constants in double; PI truncated exactly as in the reference
    const double PI_d = 3.141592;
    double phiL = asin(pow(1e-6, 1.0 / 512.0));
    double phiU = PI_d / 2.0 * (1.0 - 0.01);
    if (phiU < phiL) phiL = phiU;
    double A = PI_d - 2.0 * phiL;
    float halfA = (float)(0.5 * A);          // ang = halfA*u + (halfA + phiL)
    float mid   = (float)(0.5 * A + phiL);

    int blocks = (nrows + WARPS_PER_BLOCK - 1) / WARPS_PER_BLOCK;
    spherization_kernel<<<blocks, WARPS_PER_BLOCK * 32>>>(
        x, sc, rad, out, nrows, halfA, mid);
}